// round 15
// baseline (speedup 1.0000x reference)
#include <cuda_runtime.h>

#define N_OBSV 256
#define NYV 50
#define NXV 30
#define ITERS 400
#define LRV 0.05f
#define EPP 52                // ep pitch in floats (float4-friendly)
#define CAPC 128              // candidate capacity (R2's value)
#define INV256 0.00390625f

// dynamic smem layout (float offsets)
#define OFF_EP    0           // [256][52] = 13312
#define OFF_ZC    13312       // z[0..49], pads 50,51 = 0
#define OFF_YH    13364       // 52
#define OFF_VB    13416       // 52
#define OFF_RB    13468       // 256
#define OFF_PART  13724       // 8*52 = 416
#define OFF_WM    14140       // 8 warp maxes
#define OFF_QW    14148       // 8 warp q-sums
#define OFF_UB    14156       // 52 (sorted desc values)
#define OFF_CS    14208       // 64 (cumsum)
#define OFF_CANDV 14272       // 128
#define OFF_NC    14400       // int
#define OFF_CC    14401       // float scalar c
#define SMEM_FLOATS 14404
#define SMEM_BYTES (SMEM_FLOATS * 4)

__global__ void __launch_bounds__(256, 2)
dro_kernel(const float* __restrict__ X, const float* __restrict__ Y,
           const float* __restrict__ W, const float* __restrict__ b,
           const float* __restrict__ pdelta, const float* __restrict__ pgamma,
           float* __restrict__ out)
{
    extern __shared__ float sm[];
    float* EP    = sm + OFF_EP;
    float* ZC    = sm + OFF_ZC;
    float* YH    = sm + OFF_YH;
    float* VB    = sm + OFF_VB;
    float* RB    = sm + OFF_RB;
    float* PART  = sm + OFF_PART;
    float* WM    = sm + OFF_WM;
    float* QW    = sm + OFF_QW;
    float* UB    = sm + OFF_UB;
    float* CS    = sm + OFF_CS;
    float* CANDV = sm + OFF_CANDV;
    int*   NC    = (int*)(sm + OFF_NC);
    float* CC    = sm + OFF_CC;

    const int t    = blockIdx.x;
    const int tid  = threadIdx.x;
    const int lane = tid & 31;
    const int wid  = tid >> 5;

    const float delta = *pdelta;
    const float gamma = *pgamma;
    const float a_val = fminf(delta * 0.5f, 255.0f / 256.0f);
    int Kneed = (int)(a_val * 256.0f) + 1;
    if (Kneed > CAPC - 1) Kneed = CAPC - 1;

    // ---- prologue: ep row `tid` = Y[tid] - (X[tid] @ W^T + b) ----
    {
        float xr[NXV];
        #pragma unroll
        for (int j = 0; j < NXV; j++) xr[j] = X[tid * NXV + j];
        for (int k = 0; k < NYV; k++) {
            float s = b[k];
            #pragma unroll
            for (int j = 0; j < NXV; j++) s = fmaf(xr[j], W[k * NXV + j], s);
            EP[tid * EPP + k] = Y[tid * NYV + k] - s;
        }
        EP[tid * EPP + 50] = 0.0f;
        EP[tid * EPP + 51] = 0.0f;
    }
    if (tid < NYV)  ZC[tid] = 1.0f / 50.0f;            // z0
    if (tid == 50 || tid == 51) ZC[tid] = 0.0f;        // pads
    if (tid == 0) *CC = 0.0f;                          // c0
    __syncthreads();

    // y_hat for this CTA's scenario; emit Y_hat output row t
    if (tid < NYV) {
        float yh = Y[t * NYV + tid] - EP[t * EPP + tid];
        YH[tid] = yh;
        out[N_OBSV * NYV + t * NYV + tid] = yh;
    }

    float prevT = -1.0f;   // warm-start threshold (CTA-uniform)

    // ---- 400 PGD iterations ----
    for (int it = 0; it < ITERS; it++) {
        __syncthreads();   // B0: ZC/CC (and YH on it==0) visible

        // ===== step 1: e = ep@z - c — R2's EXACT single-chain order =====
        float e = -(*CC);
        {
            const float4* row4 = (const float4*)(EP + tid * EPP);
            const float4* z4   = (const float4*)ZC;
            #pragma unroll
            for (int j = 0; j < 13; j++) {
                float4 rv = row4[j], zv = z4[j];
                e = fmaf(rv.x, zv.x, e);
                e = fmaf(rv.y, zv.y, e);
                e = fmaf(rv.z, zv.z, e);
                e = fmaf(rv.w, zv.w, e);
            }
        }
        const float r = e * e;
        RB[tid] = r;

        // warp max partials (R2's tree)
        float wm = r;
        #pragma unroll
        for (int off = 16; off; off >>= 1)
            wm = fmaxf(wm, __shfl_xor_sync(0xffffffffu, wm, off));
        if (lane == 0) WM[wid] = wm;
        if (tid == 0) *NC = 0;
        __syncthreads();   // B1

        float maxv = WM[0];
        #pragma unroll
        for (int w = 1; w < 8; w++) maxv = fmaxf(maxv, WM[w]);

        // ===== step 2: threshold, warm-started (fp-neutral to downstream) =====
        float T = prevT;
        int c = __syncthreads_count(r < T);               // C1 (miss on iter 0)
        int goodC = -1; float goodT = 0.0f;
        if (c >= Kneed && c <= CAPC) {
            goodC = c; goodT = T;
        } else {
            float lo = 0.0f, hi = maxv;
            if (T >= 0.0f) { if (c < Kneed) lo = T; else if (T < hi) hi = T; }
            #pragma unroll 1
            for (int bs = 0; bs < 10; bs++) {
                float mid = 0.5f * (lo + hi);
                c = __syncthreads_count(r < mid);
                if (c >= Kneed && c <= CAPC) { goodC = c; goodT = mid; break; }
                if (c < Kneed) lo = mid; else hi = mid;
            }
        }
        if (goodC > 0) prevT = goodT;

        const bool iscand = (goodC > 0) && (r < goodT);
        if (iscand) CANDV[atomicAdd(NC, 1)] = r;          // order-independent use
        const int nmax = __syncthreads_count(r == maxv);  // C2: CANDV ready too

        // ===== q_i = 2 p_i e_i — R2's composition, boost every iter =====
        int cnt = 0;
        float wgt = 0.0f;
        if (goodC < 0) {                                  // fallback: full count
            const float4* r4 = (const float4*)RB;
            #pragma unroll 8
            for (int j = 0; j < N_OBSV / 4; j++) {
                float4 v = r4[j];
                cnt += (v.x < r) + (v.y < r) + (v.z < r) + (v.w < r);
            }
            wgt = fminf(fmaxf(a_val - (float)cnt * INV256, 0.0f), INV256);
        } else if (iscand) {
            int j = 0;
            #pragma unroll 1
            for (; j + 4 <= goodC; j += 4) {
                float4 v = *(const float4*)(CANDV + j);
                cnt += (v.x < r) + (v.y < r) + (v.z < r) + (v.w < r);
            }
            #pragma unroll 1
            for (; j < goodC; j++) cnt += CANDV[j] < r;
            wgt = fminf(fmaxf(a_val - (float)cnt * INV256, 0.0f), INV256);
        }
        float p = INV256 - wgt;
        if (r == maxv) p += a_val / (float)nmax;          // argmax boost (R6 semantics)
        const float q = 2.0f * p * e;

        // warp q-sums for gc (R2's tree; rides B3)
        float qs = q;
        #pragma unroll
        for (int off = 16; off; off >>= 1)
            qs += __shfl_xor_sync(0xffffffffu, qs, off);
        if (lane == 0) QW[wid] = qs;

        // ===== step 3: PART = ep^T q — R2's exact association, q via shfl =====
        {
            float acc0 = 0.0f, acc1 = 0.0f;
            const int rb = wid * 32;
            #pragma unroll 8
            for (int rr = 0; rr < 32; rr++) {
                const float qi = __shfl_sync(0xffffffffu, q, rr);  // row rb+rr
                const float* row = EP + (rb + rr) * EPP;
                acc0 = fmaf(row[lane], qi, acc0);
                if (lane < NYV - 32) acc1 = fmaf(row[lane + 32], qi, acc1);
            }
            PART[wid * 52 + lane] = acc0;
            if (lane < NYV - 32) PART[wid * 52 + lane + 32] = acc1;
        }
        __syncthreads();   // B3: PART + QW visible

        // ===== step 4: gz/gc — R2's exact sums =====
        if (tid < NYV) {
            float g = 0.0f;
            #pragma unroll
            for (int w = 0; w < 8; w++) g += PART[w * 52 + tid];
            g -= gamma * YH[tid];
            VB[tid] = ZC[tid] - LRV * g;
        } else if (tid == 64) {
            float s = 0.0f;
            #pragma unroll
            for (int w = 0; w < 8; w++) s += QW[w];
            *CC = *CC + LRV * s;                           // gc = -sum(q)
        }
        __syncthreads();   // B4: VB visible

        // ===== step 5: simplex projection — R2's exact scan version =====
        float vk = 0.0f;
        if (tid < NYV) {
            vk = VB[tid];
            int c2 = 0;
            #pragma unroll
            for (int j = 0; j < NYV; j++) {
                float vj = VB[j];
                c2 += (int)((vj < vk) | ((vj == vk) & (j < tid)));
            }
            UB[(NYV - 1) - c2] = vk;            // descending order
        }
        __syncthreads();   // B_ub

        float u = 0.0f, cs = 0.0f;
        if (tid < 64) {
            u  = (tid < NYV) ? UB[tid] : 0.0f;
            cs = u;
            #pragma unroll
            for (int off = 1; off < 32; off <<= 1) {
                float nb = __shfl_up_sync(0xffffffffu, cs, off);
                if (lane >= off) cs += nb;
            }
            if (tid == 31) CS[63] = cs;         // warp0 total
        }
        __syncthreads();   // B_cs63
        int pred = 0;
        if (tid < NYV) {
            if (tid >= 32) cs += CS[63];
            CS[tid] = cs;                       // inclusive cumsum of u
            pred = (u - (cs - 1.0f) / (float)(tid + 1)) > 0.0f;
        }
        const int rho = __syncthreads_count(pred);   // C3 (orders CS writes)
        const float tau = (CS[rho - 1] - 1.0f) / (float)rho;
        if (tid < NYV) ZC[tid] = fmaxf(vk - tau, 0.0f);
    }

    __syncthreads();
    if (tid < NYV) out[t * NYV + tid] = ZC[tid];
}

extern "C" void kernel_launch(void* const* d_in, const int* in_sizes, int n_in,
                              void* d_out, int out_size)
{
    const float* X     = (const float*)d_in[0];
    const float* Y     = (const float*)d_in[1];
    const float* W     = (const float*)d_in[2];
    const float* b     = (const float*)d_in[3];
    const float* delta = (const float*)d_in[4];
    const float* gamma = (const float*)d_in[5];
    float* out = (float*)d_out;

    cudaFuncSetAttribute(dro_kernel,
                         cudaFuncAttributeMaxDynamicSharedMemorySize,
                         SMEM_BYTES);
    dro_kernel<<<N_OBSV, 256, SMEM_BYTES>>>(X, Y, W, b, delta, gamma, out);
}